// round 9
// baseline (speedup 1.0000x reference)
#include <cuda_runtime.h>
#include <cuda_fp16.h>
#include <cuda_bf16.h>
#include <math_constants.h>

// ---------------- problem constants ----------------
#define N_NODES 100000
#define N_EDGES 1600000
#define DIM_IN  128
#define DIM_HID 128
#define DIM_OUT 64
#define NEG_SLOPE 0.2f

#define KDIM 128
#define NKS  (KDIM / 16)              // 8 k-steps of 16
#define PAD_TILES 6256                // 16-row tiles covering 100096 rows

#define SCAN_BLK 1024
#define N_SCAN_BLOCKS ((N_NODES + SCAN_BLK - 1) / SCAN_BLK)   // 98

// ---------------- scratch (device globals; no allocation allowed) ----------
__device__ __half g_h1[(size_t)N_NODES * DIM_HID];
__device__ __half g_h2[(size_t)N_NODES * DIM_OUT];
__device__ float  g_asrc[N_NODES],  g_adst[N_NODES];
__device__ float  g_asrc2[N_NODES], g_adst2[N_NODES];
__device__ float  g_p1[2 * 128];
__device__ float  g_p2[2 * 128];

// global fragment buffers: A-frags only needed for GEMM2 (written by agg1 FUSE2)
__device__ unsigned g_AfH[(size_t)PAD_TILES * NKS * 32 * 4];
__device__ unsigned g_AfL[(size_t)PAD_TILES * NKS * 32 * 4];
__device__ unsigned g_WfH1[16 * NKS * 32 * 2], g_WfL1[16 * NKS * 32 * 2];
__device__ unsigned g_WfH2[8  * NKS * 32 * 2], g_WfL2[8  * NKS * 32 * 2];

// CSR scratch
__device__ int g_cnt[N_NODES];
__device__ int g_incl[N_NODES];
__device__ int g_bsum[N_SCAN_BLOCKS];
__device__ int g_boff[N_SCAN_BLOCKS];
__device__ int g_rowptr[N_NODES + 1];
__device__ int g_woff[N_NODES];
__device__ int g_csr_src[N_EDGES];

// ---------------- CSR build ----------------
__global__ void hist_kernel(const int* __restrict__ dst) {
    int e = blockIdx.x * blockDim.x + threadIdx.x;
    if (e >= N_EDGES) return;
    int d = dst[e];
    if ((unsigned)d < N_NODES) atomicAdd(&g_cnt[d], 1);
}

__global__ void scan1_kernel() {
    __shared__ int wsum[32];
    int tid  = threadIdx.x;
    int lane = tid & 31;
    int wid  = tid >> 5;
    int i = blockIdx.x * SCAN_BLK + tid;
    int x = (i < N_NODES) ? g_cnt[i] : 0;
    #pragma unroll
    for (int off = 1; off < 32; off <<= 1) {
        int y = __shfl_up_sync(0xffffffffu, x, off);
        if (lane >= off) x += y;
    }
    if (lane == 31) wsum[wid] = x;
    __syncthreads();
    if (wid == 0) {
        int y = wsum[lane];
        #pragma unroll
        for (int off = 1; off < 32; off <<= 1) {
            int z = __shfl_up_sync(0xffffffffu, y, off);
            if (lane >= off) y += z;
        }
        wsum[lane] = y;
    }
    __syncthreads();
    if (wid > 0) x += wsum[wid - 1];
    if (i < N_NODES) g_incl[i] = x;
    if (tid == SCAN_BLK - 1) g_bsum[blockIdx.x] = x;
}

__global__ void scan2_kernel() {
    __shared__ int s[128];
    int tid = threadIdx.x;
    int v0 = (tid < N_SCAN_BLOCKS) ? g_bsum[tid] : 0;
    s[tid] = v0;
    __syncthreads();
    #pragma unroll
    for (int off = 1; off < 128; off <<= 1) {
        int v = (tid >= off) ? s[tid - off] : 0;
        __syncthreads();
        s[tid] += v;
        __syncthreads();
    }
    if (tid < N_SCAN_BLOCKS) g_boff[tid] = s[tid] - v0;
}

__global__ void scan3_kernel() {
    int i = blockIdx.x * blockDim.x + threadIdx.x;
    if (i >= N_NODES) return;
    int excl = g_incl[i] - g_cnt[i] + g_boff[i / SCAN_BLK];
    g_rowptr[i] = excl;
    g_woff[i]   = excl;
    if (i == 0) g_rowptr[N_NODES] = N_EDGES;
}

__global__ void scatter_kernel(const int* __restrict__ src, const int* __restrict__ dst) {
    int e = blockIdx.x * blockDim.x + threadIdx.x;
    if (e >= N_EDGES) return;
    int s = src[e];
    int d = dst[e];
    if ((unsigned)s >= N_NODES || (unsigned)d >= N_NODES) return;
    int pos = atomicAdd(&g_woff[d], 1);
    g_csr_src[pos] = s;
}

// ---------------- merged p-vectors for both layers ----------------
__global__ void compute_p_all_kernel(const float* __restrict__ W1s, const float* __restrict__ a1s,
                                     const float* __restrict__ W1d, const float* __restrict__ a1d,
                                     const float* __restrict__ W2s, const float* __restrict__ a2s,
                                     const float* __restrict__ W2d, const float* __restrict__ a2d) {
    int i = threadIdx.x;  // 0..127
    if (blockIdx.x == 0) {
        float s = 0.f, d = 0.f;
        for (int c = 0; c < DIM_HID; c++) {
            s += W1s[i * DIM_HID + c] * a1s[c];
            d += W1d[i * DIM_HID + c] * a1d[c];
        }
        g_p1[i] = s;
        g_p1[128 + i] = d;
    } else {
        float s = 0.f, d = 0.f;
        for (int c = 0; c < DIM_OUT; c++) {
            s += W2s[i * DIM_OUT + c] * a2s[c];
            d += W2d[i * DIM_OUT + c] * a2d[c];
        }
        g_p2[i] = s;
        g_p2[128 + i] = d;
    }
}

// ---------------- bf16 split / pack helpers ----------------
__device__ __forceinline__ void split_bf16(float x, __nv_bfloat16& h, __nv_bfloat16& l) {
    h = __float2bfloat16_rn(x);
    l = __float2bfloat16_rn(x - __bfloat162float(h));
}
__device__ __forceinline__ unsigned pack_bf16(__nv_bfloat16 a, __nv_bfloat16 b) {
    __nv_bfloat162 t;
    t.x = a; t.y = b;
    return *(unsigned*)&t;
}

// GEMM2 A-frag scatter (global; lane holds cols 4l..4l+3 of node n)
__device__ __forceinline__ void write_frag_row(int n, int lane, float4 v) {
    int tile = n >> 4;
    int g    = n & 7;
    int r8   = (n >> 3) & 1;
    int ks   = lane >> 2;
    int j    = lane & 3;
    int t0   = ((4 * j) & 7) >> 1;
    int reg  = r8 + ((j & 2) ? 2 : 0);
    size_t blockbase = (size_t)(tile * 8 + ks) * 128;
    __nv_bfloat16 h0, l0, h1, l1, h2, l2, h3, l3;
    split_bf16(v.x, h0, l0); split_bf16(v.y, h1, l1);
    split_bf16(v.z, h2, l2); split_bf16(v.w, h3, l3);
    size_t w0 = blockbase + (size_t)(g * 4 + t0) * 4 + reg;
    size_t w1 = blockbase + (size_t)(g * 4 + t0 + 1) * 4 + reg;
    g_AfH[w0] = pack_bf16(h0, h1);
    g_AfL[w0] = pack_bf16(l0, l1);
    g_AfH[w1] = pack_bf16(h2, h3);
    g_AfL[w1] = pack_bf16(l2, l3);
}

// ---------------- merged W conversion (both layers) ----------------
__global__ void convertW_all_kernel(const float* __restrict__ W1, const float* __restrict__ W2) {
    bool first = blockIdx.x < (DIM_HID / 8);
    int ct = first ? blockIdx.x : blockIdx.x - (DIM_HID / 8);
    int COUT = first ? DIM_HID : DIM_OUT;
    const float* W = first ? W1 : W2;
    unsigned* WfH = first ? g_WfH1 : g_WfH2;
    unsigned* WfL = first ? g_WfL1 : g_WfL2;

    int ks   = threadIdx.x >> 5;
    int lane = threadIdx.x & 31;
    int g = lane >> 2, t = lane & 3;
    size_t base = (((size_t)ct * NKS + ks) * 32 + lane) * 2;
    #pragma unroll
    for (int r = 0; r < 2; r++) {
        int k   = ks * 16 + 2 * t + r * 8;
        int col = ct * 8 + g;
        float e0 = W[(size_t)k * COUT + col];
        float e1 = W[(size_t)(k + 1) * COUT + col];
        __nv_bfloat16 h0, l0, h1, l1;
        split_bf16(e0, h0, l0);
        split_bf16(e1, h1, l1);
        WfH[base + r] = pack_bf16(h0, h1);
        WfL[base + r] = pack_bf16(l0, l1);
    }
}

// ---------------- mma.sync bf16 ----------------
__device__ __forceinline__ void mma_bf16(float c[4], const unsigned a[4], const unsigned b[2]) {
    asm volatile(
        "mma.sync.aligned.m16n8k16.row.col.f32.bf16.bf16.f32 "
        "{%0,%1,%2,%3}, {%4,%5,%6,%7}, {%8,%9}, {%0,%1,%2,%3};"
        : "+f"(c[0]), "+f"(c[1]), "+f"(c[2]), "+f"(c[3])
        : "r"(a[0]), "r"(a[1]), "r"(a[2]), "r"(a[3]), "r"(b[0]), "r"(b[1]));
}

// ======= GEMM1 fused: reads x once, a_src/a_dst dots + smem frags + mma ======
// smem: [0:8192) words A-hi frags, [8192:16384) words A-lo frags  (64KB)
#define G1_WORDS 8192

__global__ __launch_bounds__(256)
void gemm1_fused_kernel(const float* __restrict__ X, __half* __restrict__ H, int nrows,
                        const unsigned* __restrict__ WfHp, const unsigned* __restrict__ WfLp) {
    extern __shared__ unsigned sf[];
    int tid  = threadIdx.x;
    int wid  = tid >> 5;
    int lane = tid & 31;

    // ---- prologue: warp w loads rows 16w..16w+15; dots + smem frag scatter ----
    {
        float4 ps = ((const float4*)g_p1)[lane];
        float4 pd = ((const float4*)(g_p1 + 128))[lane];
        int ks = lane >> 2;
        int j  = lane & 3;
        int t0 = ((4 * j) & 7) >> 1;
        int rg = (j & 2) ? 2 : 0;
        for (int rr = 0; rr < 16; rr++) {
            int row  = wid * 16 + rr;
            int grow = blockIdx.x * 128 + row;
            float4 v = make_float4(0.f, 0.f, 0.f, 0.f);
            if (grow < nrows) v = ((const float4*)(X + (size_t)grow * 128))[lane];
            float s = v.x * ps.x + v.y * ps.y + v.z * ps.z + v.w * ps.w;
            float d = v.x * pd.x + v.y * pd.y + v.z * pd.z + v.w * pd.w;
            #pragma unroll
            for (int o = 16; o > 0; o >>= 1) {
                s += __shfl_xor_sync(0xffffffffu, s, o);
                d += __shfl_xor_sync(0xffffffffu, d, o);
            }
            if (lane == 0 && grow < nrows) {
                g_asrc[grow] = s;
                g_adst[grow] = d;
            }
            int tile = row >> 4;
            int g    = row & 7;
            int reg  = ((row >> 3) & 1) + rg;
            int base = (tile * 8 + ks) * 128;
            __nv_bfloat16 h0, l0, h1, l1, h2, l2, h3, l3;
            split_bf16(v.x, h0, l0); split_bf16(v.y, h1, l1);
            split_bf16(v.z, h2, l2); split_bf16(v.w, h3, l3);
            int w0 = base + (g * 4 + t0) * 4 + reg;
            int w1 = base + (g * 4 + t0 + 1) * 4 + reg;
            sf[w0] = pack_bf16(h0, h1);
            sf[w1] = pack_bf16(h2, h3);
            sf[G1_WORDS + w0] = pack_bf16(l0, l1);
            sf[G1_WORDS + w1] = pack_bf16(l2, l3);
        }
    }
    __syncthreads();

    // ---- mainloop: A frags from smem (LDS.128), B frags from global (L1/L2) ----
    int g = lane >> 2, t = lane & 3;
    int warp_m = wid >> 1;
    int warp_n = wid & 1;
    int base_tile = warp_m * 2;

    const uint4* AH = (const uint4*)sf;
    const uint4* AL = (const uint4*)(sf + G1_WORDS);
    const uint2* WfH = (const uint2*)WfHp;
    const uint2* WfL = (const uint2*)WfLp;

    float c[2][8][4];
    #pragma unroll
    for (int mt = 0; mt < 2; mt++)
        #pragma unroll
        for (int nt = 0; nt < 8; nt++)
            #pragma unroll
            for (int i = 0; i < 4; i++) c[mt][nt][i] = 0.0f;

    #pragma unroll
    for (int ks = 0; ks < NKS; ks++) {
        uint4 Ah[2], Al[2];
        #pragma unroll
        for (int mt = 0; mt < 2; mt++) {
            int ai = ((base_tile + mt) * 8 + ks) * 32 + lane;
            Ah[mt] = AH[ai];
            Al[mt] = AL[ai];
        }
        #pragma unroll
        for (int nt = 0; nt < 8; nt++) {
            int ct = warp_n * 8 + nt;
            size_t bi = ((size_t)ct * NKS + ks) * 32 + lane;
            uint2 Bh = WfH[bi];
            uint2 Bl = WfL[bi];
            #pragma unroll
            for (int mt = 0; mt < 2; mt++) {
                mma_bf16(c[mt][nt], (const unsigned*)&Ah[mt], (const unsigned*)&Bh);
                mma_bf16(c[mt][nt], (const unsigned*)&Ah[mt], (const unsigned*)&Bl);
                mma_bf16(c[mt][nt], (const unsigned*)&Al[mt], (const unsigned*)&Bh);
            }
        }
    }

    // ---- epilogue ----
    #pragma unroll
    for (int mt = 0; mt < 2; mt++) {
        int r0 = blockIdx.x * 128 + warp_m * 32 + mt * 16 + g;
        #pragma unroll
        for (int nt = 0; nt < 8; nt++) {
            int col = (warp_n * 8 + nt) * 8 + 2 * t;
            if (r0 < nrows)
                *(__half2*)&H[(size_t)r0 * 128 + col] =
                    __floats2half2_rn(c[mt][nt][0], c[mt][nt][1]);
            if (r0 + 8 < nrows)
                *(__half2*)&H[(size_t)(r0 + 8) * 128 + col] =
                    __floats2half2_rn(c[mt][nt][2], c[mt][nt][3]);
        }
    }
}

// ---------------- GEMM2: frag path (A frags written by agg1 FUSE2) ----------
template<int COUT>
__global__ __launch_bounds__(256, 2)
void gemm_frag_kernel(__half* __restrict__ H, int nrows,
                      const unsigned* __restrict__ WfHp, const unsigned* __restrict__ WfLp) {
    constexpr int WN = (COUT == 128) ? 2 : 1;
    constexpr int WMCNT = 8 / WN;
    constexpr int ROWS = WMCNT * 32;

    int wid  = threadIdx.x >> 5;
    int lane = threadIdx.x & 31;
    int g = lane >> 2, t = lane & 3;
    int warp_m = (COUT == 128) ? (wid >> 1) : wid;
    int warp_n = (COUT == 128) ? (wid & 1) : 0;
    int base_tile = blockIdx.x * (ROWS / 16) + warp_m * 2;

    const uint4* AfH = (const uint4*)g_AfH;
    const uint4* AfL = (const uint4*)g_AfL;
    const uint2* WfH = (const uint2*)WfHp;
    const uint2* WfL = (const uint2*)WfLp;

    float c[2][8][4];
    #pragma unroll
    for (int mt = 0; mt < 2; mt++)
        #pragma unroll
        for (int nt = 0; nt < 8; nt++)
            #pragma unroll
            for (int i = 0; i < 4; i++) c[mt][nt][i] = 0.0f;

    #pragma unroll
    for (int ks = 0; ks < NKS; ks++) {
        uint4 Ah[2], Al[2];
        #pragma unroll
        for (int mt = 0; mt < 2; mt++) {
            size_t ai = ((size_t)(base_tile + mt) * NKS + ks) * 32 + lane;
            Ah[mt] = AfH[ai];
            Al[mt] = AfL[ai];
        }
        #pragma unroll
        for (int nt = 0; nt < 8; nt++) {
            int ct = warp_n * 8 + nt;
            size_t bi = ((size_t)ct * NKS + ks) * 32 + lane;
            uint2 Bh = WfH[bi];
            uint2 Bl = WfL[bi];
            #pragma unroll
            for (int mt = 0; mt < 2; mt++) {
                mma_bf16(c[mt][nt], (const unsigned*)&Ah[mt], (const unsigned*)&Bh);
                mma_bf16(c[mt][nt], (const unsigned*)&Ah[mt], (const unsigned*)&Bl);
                mma_bf16(c[mt][nt], (const unsigned*)&Al[mt], (const unsigned*)&Bh);
            }
        }
    }

    #pragma unroll
    for (int mt = 0; mt < 2; mt++) {
        int r0 = blockIdx.x * ROWS + warp_m * 32 + mt * 16 + g;
        #pragma unroll
        for (int nt = 0; nt < 8; nt++) {
            int col = (warp_n * 8 + nt) * 8 + 2 * t;
            if (r0 < nrows)
                *(__half2*)&H[(size_t)r0 * COUT + col] =
                    __floats2half2_rn(c[mt][nt][0], c[mt][nt][1]);
            if (r0 + 8 < nrows)
                *(__half2*)&H[(size_t)(r0 + 8) * COUT + col] =
                    __floats2half2_rn(c[mt][nt][2], c[mt][nt][3]);
        }
    }
}

// ---------------- fused softmax + aggregate (multi-edge unroll, same lanes) --
#define LCACHE 128
template<int C, bool RELU, bool FUSE2>
__global__ void node_aggregate_kernel(const __half* __restrict__ h,
                                      const float* __restrict__ bias,
                                      float* __restrict__ out,
                                      const float* __restrict__ asrc,
                                      const float* __restrict__ adst) {
    constexpr int U = (C == 128) ? 2 : 4;     // sequential edges in flight per lane

    __shared__ float lc[8][LCACHE];
    int warp = (blockIdx.x * blockDim.x + threadIdx.x) >> 5;
    int w    = (threadIdx.x >> 5);
    int lane = threadIdx.x & 31;
    if (warp >= N_NODES) return;
    int n   = warp;
    int beg = g_rowptr[n];
    int end = g_rowptr[n + 1];
    float ad = adst[n];

    // pass 1: logits -> cache, warp max
    float m = -CUDART_INF_F;
    for (int i = beg + lane; i < end; i += 32) {
        int s = g_csr_src[i];
        float l = asrc[s] + ad;
        l = (l > 0.0f) ? l : NEG_SLOPE * l;
        int off = i - beg;
        if (off < LCACHE) lc[w][off] = l;
        m = fmaxf(m, l);
    }
    #pragma unroll
    for (int o = 16; o > 0; o >>= 1)
        m = fmaxf(m, __shfl_xor_sync(0xffffffffu, m, o));
    __syncwarp();

    // pass 2: U edges per iteration, same column-lanes (no cross-lane reduce)
    float den = 0.0f;
    float a0 = 0.f, a1 = 0.f, a2 = 0.f, a3 = 0.f;
    int i = beg;
    for (; i + U <= end; i += U) {
        float ev[U];
        int   s[U];
        #pragma unroll
        for (int u = 0; u < U; u++) {
            int off = i + u - beg;
            float l;
            if (off < LCACHE) {
                l = lc[w][off];
            } else {
                int sx = g_csr_src[i + u];
                l = asrc[sx] + ad;
                l = (l > 0.0f) ? l : NEG_SLOPE * l;
            }
            ev[u] = __expf(l - m);
            den  += ev[u];
            s[u]  = g_csr_src[i + u];
        }
        if (C == 128) {
            uint2 raw[U];
            #pragma unroll
            for (int u = 0; u < U; u++)
                raw[u] = ((const uint2*)(h + (size_t)s[u] * C))[lane];
            #pragma unroll
            for (int u = 0; u < U; u++) {
                float2 f01 = __half22float2(*(const __half2*)&raw[u].x);
                float2 f23 = __half22float2(*(const __half2*)&raw[u].y);
                a0 += ev[u] * f01.x; a1 += ev[u] * f01.y;
                a2 += ev[u] * f23.x; a3 += ev[u] * f23.y;
            }
        } else {
            __half2 raw[U];
            #pragma unroll
            for (int u = 0; u < U; u++)
                raw[u] = ((const __half2*)(h + (size_t)s[u] * C))[lane];
            #pragma unroll
            for (int u = 0; u < U; u++) {
                float2 f = __half22float2(raw[u]);
                a0 += ev[u] * f.x; a1 += ev[u] * f.y;
            }
        }
    }
    for (; i < end; i++) {
        int off = i - beg;
        float l;
        if (off < LCACHE) {
            l = lc[w][off];
        } else {
            int sx = g_csr_src[i];
            l = asrc[sx] + ad;
            l = (l > 0.0f) ? l : NEG_SLOPE * l;
        }
        float ev = __expf(l - m);
        den += ev;
        int s = g_csr_src[i];
        const __half* hp = h + (size_t)s * C;
        if (C == 128) {
            uint2 raw = ((const uint2*)hp)[lane];
            float2 f01 = __half22float2(*(const __half2*)&raw.x);
            float2 f23 = __half22float2(*(const __half2*)&raw.y);
            a0 += ev * f01.x; a1 += ev * f01.y;
            a2 += ev * f23.x; a3 += ev * f23.y;
        } else {
            __half2 raw = ((const __half2*)hp)[lane];
            float2 f = __half22float2(raw);
            a0 += ev * f.x; a1 += ev * f.y;
        }
    }

    float inv = 1.0f / (den + 1e-16f);
    if (C == 128) {
        float4 b = ((const float4*)bias)[lane];
        float4 r;
        r.x = a0 * inv + b.x; r.y = a1 * inv + b.y;
        r.z = a2 * inv + b.z; r.w = a3 * inv + b.w;
        if (RELU) {
            r.x = fmaxf(r.x, 0.f); r.y = fmaxf(r.y, 0.f);
            r.z = fmaxf(r.z, 0.f); r.w = fmaxf(r.w, 0.f);
        }
        if (FUSE2) {
            float4 ps = ((const float4*)g_p2)[lane];
            float4 pd = ((const float4*)(g_p2 + 128))[lane];
            float s2 = r.x * ps.x + r.y * ps.y + r.z * ps.z + r.w * ps.w;
            float d2 = r.x * pd.x + r.y * pd.y + r.z * pd.z + r.w * pd.w;
            #pragma unroll
            for (int o = 16; o > 0; o >>= 1) {
                s2 += __shfl_xor_sync(0xffffffffu, s2, o);
                d2 += __shfl_xor_sync(0xffffffffu, d2, o);
            }
            if (lane == 0) {
                g_asrc2[n] = s2;
                g_adst2[n] = d2;
            }
            write_frag_row(n, lane, r);
        } else {
            ((float4*)(out + (size_t)n * C))[lane] = r;
        }
    } else {
        float2 b = ((const float2*)bias)[lane];
        float2 r;
        r.x = a0 * inv + b.x; r.y = a1 * inv + b.y;
        if (RELU) { r.x = fmaxf(r.x, 0.f); r.y = fmaxf(r.y, 0.f); }
        ((float2*)(out + (size_t)n * C))[lane] = r;
    }
}

// ---------------- launch ----------------
extern "C" void kernel_launch(void* const* d_in, const int* in_sizes, int n_in,
                              void* d_out, int out_size) {
    const float* x   = (const float*)d_in[0];
    const int*   ei  = (const int*)d_in[1];
    const float* W1s = (const float*)d_in[2];
    const float* W1d = (const float*)d_in[3];
    const float* a1s = (const float*)d_in[4];
    const float* a1d = (const float*)d_in[5];
    const float* b1  = (const float*)d_in[6];
    const float* W2s = (const float*)d_in[7];
    const float* W2d = (const float*)d_in[8];
    const float* a2s = (const float*)d_in[9];
    const float* a2d = (const float*)d_in[10];
    const float* b2  = (const float*)d_in[11];
    float* out = (float*)d_out;

    const int* srcp = ei;
    const int* dstp = ei + N_EDGES;

    void *p_cnt, *p_h1, *p_h2, *p_WfH1, *p_WfL1, *p_WfH2, *p_WfL2;
    void *p_asrc, *p_adst, *p_asrc2, *p_adst2;
    cudaGetSymbolAddress(&p_cnt, g_cnt);
    cudaGetSymbolAddress(&p_h1, g_h1);
    cudaGetSymbolAddress(&p_h2, g_h2);
    cudaGetSymbolAddress(&p_WfH1, g_WfH1);
    cudaGetSymbolAddress(&p_WfL1, g_WfL1);
    cudaGetSymbolAddress(&p_WfH2, g_WfH2);
    cudaGetSymbolAddress(&p_WfL2, g_WfL2);
    cudaGetSymbolAddress(&p_asrc, g_asrc);
    cudaGetSymbolAddress(&p_adst, g_adst);
    cudaGetSymbolAddress(&p_asrc2, g_asrc2);
    cudaGetSymbolAddress(&p_adst2, g_adst2);
    __half* h1 = (__half*)p_h1;
    __half* h2 = (__half*)p_h2;

    static cudaStream_t s_side = nullptr;
    static cudaEvent_t ev_fork = nullptr, ev_join = nullptr;
    if (!s_side) {
        cudaStreamCreateWithFlags(&s_side, cudaStreamNonBlocking);
        cudaEventCreateWithFlags(&ev_fork, cudaEventDisableTiming);
        cudaEventCreateWithFlags(&ev_join, cudaEventDisableTiming);
        cudaFuncSetAttribute(gemm1_fused_kernel,
                             cudaFuncAttributeMaxDynamicSharedMemorySize, 65536);
    }

    const int TB = 256;
    const int edgeBlocks = (N_EDGES + TB - 1) / TB;
    const int nodeBlocks = (N_NODES + TB - 1) / TB;
    const int nodeWarpBlocks = (N_NODES * 32 + TB - 1) / TB;

    // ---- fork: CSR build on side stream ----
    cudaEventRecord(ev_fork, 0);
    cudaStreamWaitEvent(s_side, ev_fork, 0);
    cudaMemsetAsync(p_cnt, 0, N_NODES * sizeof(int), s_side);
    hist_kernel<<<edgeBlocks, TB, 0, s_side>>>(dstp);
    scan1_kernel<<<N_SCAN_BLOCKS, SCAN_BLK, 0, s_side>>>();
    scan2_kernel<<<1, 128, 0, s_side>>>();
    scan3_kernel<<<nodeBlocks, TB, 0, s_side>>>();
    scatter_kernel<<<edgeBlocks, TB, 0, s_side>>>(srcp, dstp);
    cudaEventRecord(ev_join, s_side);

    // ---- main chain ----
    compute_p_all_kernel<<<2, 128>>>(W1s, a1s, W1d, a1d, W2s, a2s, W2d, a2d);
    convertW_all_kernel<<<DIM_HID / 8 + DIM_OUT / 8, 256>>>(W1s, W2s);
    gemm1_fused_kernel<<<(N_NODES + 127) / 128, 256, 65536>>>(
        x, h1, N_NODES, (unsigned*)p_WfH1, (unsigned*)p_WfL1);

    // ---- join: aggregate needs CSR + gemm1 ----
    cudaStreamWaitEvent(0, ev_join, 0);
    node_aggregate_kernel<DIM_HID, true, true><<<nodeWarpBlocks, TB>>>(
        h1, b1, nullptr, (const float*)p_asrc, (const float*)p_adst);
    gemm_frag_kernel<DIM_OUT><<<(N_NODES + 255) / 256, 256>>>(h2, N_NODES,
                                                              (unsigned*)p_WfH2, (unsigned*)p_WfL2);
    node_aggregate_kernel<DIM_OUT, false, false><<<nodeWarpBlocks, TB>>>(
        h2, b2, out, (const float*)p_asrc2, (const float*)p_adst2);

    (void)in_sizes; (void)n_in; (void)out_size;
}

// round 10
// speedup vs baseline: 1.1363x; 1.1363x over previous
#include <cuda_runtime.h>
#include <cuda_fp16.h>
#include <cuda_bf16.h>
#include <math_constants.h>

// ---------------- problem constants ----------------
#define N_NODES 100000
#define N_EDGES 1600000
#define DIM_IN  128
#define DIM_HID 128
#define DIM_OUT 64
#define NEG_SLOPE 0.2f

#define KDIM 128
#define NKS  (KDIM / 16)              // 8 k-steps of 16
#define PAD_TILES 6256                // covers 782*8 (gemm1) and 391*16 (gemm2)

#define SCAN_BLK 1024
#define N_SCAN_BLOCKS ((N_NODES + SCAN_BLK - 1) / SCAN_BLK)   // 98

// ---------------- scratch (device globals; no allocation allowed) ----------
__device__ __half g_h1[(size_t)N_NODES * DIM_HID];
__device__ __half g_h2[(size_t)N_NODES * DIM_OUT];
__device__ float  g_asrc[N_NODES],  g_adst[N_NODES];
__device__ float  g_asrc2[N_NODES], g_adst2[N_NODES];
__device__ float  g_p1[2 * 128];
__device__ float  g_p2[2 * 128];

__device__ unsigned g_AfH[(size_t)PAD_TILES * NKS * 32 * 4];
__device__ unsigned g_AfL[(size_t)PAD_TILES * NKS * 32 * 4];
__device__ unsigned g_WfH1[16 * NKS * 32 * 2], g_WfL1[16 * NKS * 32 * 2];
__device__ unsigned g_WfH2[8  * NKS * 32 * 2], g_WfL2[8  * NKS * 32 * 2];

// CSR scratch
__device__ int g_cnt[N_NODES];
__device__ int g_incl[N_NODES];
__device__ int g_bsum[N_SCAN_BLOCKS];
__device__ int g_boff[N_SCAN_BLOCKS];
__device__ int g_rowptr[N_NODES + 1];
__device__ int g_woff[N_NODES];
__device__ int g_csr_src[N_EDGES];

// ---------------- CSR build ----------------
__global__ void hist_kernel(const int* __restrict__ dst) {
    int e = blockIdx.x * blockDim.x + threadIdx.x;
    if (e >= N_EDGES) return;
    int d = dst[e];
    if ((unsigned)d < N_NODES) atomicAdd(&g_cnt[d], 1);
}

__global__ void scan1_kernel() {
    __shared__ int wsum[32];
    int tid  = threadIdx.x;
    int lane = tid & 31;
    int wid  = tid >> 5;
    int i = blockIdx.x * SCAN_BLK + tid;
    int x = (i < N_NODES) ? g_cnt[i] : 0;
    #pragma unroll
    for (int off = 1; off < 32; off <<= 1) {
        int y = __shfl_up_sync(0xffffffffu, x, off);
        if (lane >= off) x += y;
    }
    if (lane == 31) wsum[wid] = x;
    __syncthreads();
    if (wid == 0) {
        int y = wsum[lane];
        #pragma unroll
        for (int off = 1; off < 32; off <<= 1) {
            int z = __shfl_up_sync(0xffffffffu, y, off);
            if (lane >= off) y += z;
        }
        wsum[lane] = y;
    }
    __syncthreads();
    if (wid > 0) x += wsum[wid - 1];
    if (i < N_NODES) g_incl[i] = x;
    if (tid == SCAN_BLK - 1) g_bsum[blockIdx.x] = x;
}

__global__ void scan2_kernel() {
    __shared__ int s[128];
    int tid = threadIdx.x;
    int v0 = (tid < N_SCAN_BLOCKS) ? g_bsum[tid] : 0;
    s[tid] = v0;
    __syncthreads();
    #pragma unroll
    for (int off = 1; off < 128; off <<= 1) {
        int v = (tid >= off) ? s[tid - off] : 0;
        __syncthreads();
        s[tid] += v;
        __syncthreads();
    }
    if (tid < N_SCAN_BLOCKS) g_boff[tid] = s[tid] - v0;
}

__global__ void scan3_kernel() {
    int i = blockIdx.x * blockDim.x + threadIdx.x;
    if (i >= N_NODES) return;
    int excl = g_incl[i] - g_cnt[i] + g_boff[i / SCAN_BLK];
    g_rowptr[i] = excl;
    g_woff[i]   = excl;
    if (i == 0) g_rowptr[N_NODES] = N_EDGES;
}

__global__ void scatter_kernel(const int* __restrict__ src, const int* __restrict__ dst) {
    int e = blockIdx.x * blockDim.x + threadIdx.x;
    if (e >= N_EDGES) return;
    int s = src[e];
    int d = dst[e];
    if ((unsigned)s >= N_NODES || (unsigned)d >= N_NODES) return;
    int pos = atomicAdd(&g_woff[d], 1);
    g_csr_src[pos] = s;
}

// ---------------- merged p-vectors for both layers ----------------
__global__ void compute_p_all_kernel(const float* __restrict__ W1s, const float* __restrict__ a1s,
                                     const float* __restrict__ W1d, const float* __restrict__ a1d,
                                     const float* __restrict__ W2s, const float* __restrict__ a2s,
                                     const float* __restrict__ W2d, const float* __restrict__ a2d) {
    int i = threadIdx.x;  // 0..127
    if (blockIdx.x == 0) {
        float s = 0.f, d = 0.f;
        for (int c = 0; c < DIM_HID; c++) {
            s += W1s[i * DIM_HID + c] * a1s[c];
            d += W1d[i * DIM_HID + c] * a1d[c];
        }
        g_p1[i] = s;
        g_p1[128 + i] = d;
    } else {
        float s = 0.f, d = 0.f;
        for (int c = 0; c < DIM_OUT; c++) {
            s += W2s[i * DIM_OUT + c] * a2s[c];
            d += W2d[i * DIM_OUT + c] * a2d[c];
        }
        g_p2[i] = s;
        g_p2[128 + i] = d;
    }
}

// ---------------- bf16 split / pack / frag-scatter helpers ----------------
__device__ __forceinline__ void split_bf16(float x, __nv_bfloat16& h, __nv_bfloat16& l) {
    h = __float2bfloat16_rn(x);
    l = __float2bfloat16_rn(x - __bfloat162float(h));
}
__device__ __forceinline__ unsigned pack_bf16(__nv_bfloat16 a, __nv_bfloat16 b) {
    __nv_bfloat162 t;
    t.x = a; t.y = b;
    return *(unsigned*)&t;
}

// lane holds cols 4l..4l+3 of node n (32-lane layout)
__device__ __forceinline__ void write_frag_row(int n, int lane, float4 v) {
    int tile = n >> 4;
    int g    = n & 7;
    int r8   = (n >> 3) & 1;
    int ks   = lane >> 2;
    int j    = lane & 3;
    int t0   = ((4 * j) & 7) >> 1;
    int reg  = r8 + ((j & 2) ? 2 : 0);
    size_t blockbase = (size_t)(tile * 8 + ks) * 128;
    __nv_bfloat16 h0, l0, h1, l1, h2, l2, h3, l3;
    split_bf16(v.x, h0, l0); split_bf16(v.y, h1, l1);
    split_bf16(v.z, h2, l2); split_bf16(v.w, h3, l3);
    size_t w0 = blockbase + (size_t)(g * 4 + t0) * 4 + reg;
    size_t w1 = blockbase + (size_t)(g * 4 + t0 + 1) * 4 + reg;
    g_AfH[w0] = pack_bf16(h0, h1);
    g_AfL[w0] = pack_bf16(l0, l1);
    g_AfH[w1] = pack_bf16(h2, h3);
    g_AfL[w1] = pack_bf16(l2, l3);
}

// ---------------- row_prep: a_src/a_dst dots + A-fragments, one pass over x ----
__global__ void row_prep_kernel(const float* __restrict__ feat) {
    int warp = (blockIdx.x * blockDim.x + threadIdx.x) >> 5;
    int lane = threadIdx.x & 31;
    if (warp >= PAD_TILES * 16) return;
    if (warp >= N_NODES) {
        write_frag_row(warp, lane, make_float4(0.f, 0.f, 0.f, 0.f));
        return;
    }
    float4 v = ((const float4*)(feat + (size_t)warp * 128))[lane];
    float4 ps = ((const float4*)g_p1)[lane];
    float4 pd = ((const float4*)(g_p1 + 128))[lane];
    float s = v.x * ps.x + v.y * ps.y + v.z * ps.z + v.w * ps.w;
    float d = v.x * pd.x + v.y * pd.y + v.z * pd.z + v.w * pd.w;
    #pragma unroll
    for (int o = 16; o > 0; o >>= 1) {
        s += __shfl_xor_sync(0xffffffffu, s, o);
        d += __shfl_xor_sync(0xffffffffu, d, o);
    }
    if (lane == 0) {
        g_asrc[warp] = s;
        g_adst[warp] = d;
    }
    write_frag_row(warp, lane, v);
}

// ---------------- merged W conversion (both layers) ----------------
__global__ void convertW_all_kernel(const float* __restrict__ W1, const float* __restrict__ W2) {
    bool first = blockIdx.x < (DIM_HID / 8);
    int ct = first ? blockIdx.x : blockIdx.x - (DIM_HID / 8);
    int COUT = first ? DIM_HID : DIM_OUT;
    const float* W = first ? W1 : W2;
    unsigned* WfH = first ? g_WfH1 : g_WfH2;
    unsigned* WfL = first ? g_WfL1 : g_WfL2;

    int ks   = threadIdx.x >> 5;
    int lane = threadIdx.x & 31;
    int g = lane >> 2, t = lane & 3;
    size_t base = (((size_t)ct * NKS + ks) * 32 + lane) * 2;
    #pragma unroll
    for (int r = 0; r < 2; r++) {
        int k   = ks * 16 + 2 * t + r * 8;
        int col = ct * 8 + g;
        float e0 = W[(size_t)k * COUT + col];
        float e1 = W[(size_t)(k + 1) * COUT + col];
        __nv_bfloat16 h0, l0, h1, l1;
        split_bf16(e0, h0, l0);
        split_bf16(e1, h1, l1);
        WfH[base + r] = pack_bf16(h0, h1);
        WfL[base + r] = pack_bf16(l0, l1);
    }
}

// ---------------- bf16 3x mma GEMM (no smem, no sync) ----------------
__device__ __forceinline__ void mma_bf16(float c[4], const unsigned a[4], const unsigned b[2]) {
    asm volatile(
        "mma.sync.aligned.m16n8k16.row.col.f32.bf16.bf16.f32 "
        "{%0,%1,%2,%3}, {%4,%5,%6,%7}, {%8,%9}, {%0,%1,%2,%3};"
        : "+f"(c[0]), "+f"(c[1]), "+f"(c[2]), "+f"(c[3])
        : "r"(a[0]), "r"(a[1]), "r"(a[2]), "r"(a[3]), "r"(b[0]), "r"(b[1]));
}

template<int COUT>
__global__ __launch_bounds__(256, 2)
void gemm_frag_kernel(__half* __restrict__ H, int nrows,
                      const unsigned* __restrict__ WfHp, const unsigned* __restrict__ WfLp) {
    constexpr int WN = (COUT == 128) ? 2 : 1;
    constexpr int WMCNT = 8 / WN;
    constexpr int ROWS = WMCNT * 32;

    int wid  = threadIdx.x >> 5;
    int lane = threadIdx.x & 31;
    int g = lane >> 2, t = lane & 3;
    int warp_m = (COUT == 128) ? (wid >> 1) : wid;
    int warp_n = (COUT == 128) ? (wid & 1) : 0;
    int base_tile = blockIdx.x * (ROWS / 16) + warp_m * 2;

    const uint4* AfH = (const uint4*)g_AfH;
    const uint4* AfL = (const uint4*)g_AfL;
    const uint2* WfH = (const uint2*)WfHp;
    const uint2* WfL = (const uint2*)WfLp;

    float c[2][8][4];
    #pragma unroll
    for (int mt = 0; mt < 2; mt++)
        #pragma unroll
        for (int nt = 0; nt < 8; nt++)
            #pragma unroll
            for (int i = 0; i < 4; i++) c[mt][nt][i] = 0.0f;

    #pragma unroll
    for (int ks = 0; ks < NKS; ks++) {
        uint4 Ah[2], Al[2];
        #pragma unroll
        for (int mt = 0; mt < 2; mt++) {
            size_t ai = ((size_t)(base_tile + mt) * NKS + ks) * 32 + lane;
            Ah[mt] = AfH[ai];
            Al[mt] = AfL[ai];
        }
        #pragma unroll
        for (int nt = 0; nt < 8; nt++) {
            int ct = warp_n * 8 + nt;
            size_t bi = ((size_t)ct * NKS + ks) * 32 + lane;
            uint2 Bh = WfH[bi];
            uint2 Bl = WfL[bi];
            #pragma unroll
            for (int mt = 0; mt < 2; mt++) {
                mma_bf16(c[mt][nt], (const unsigned*)&Ah[mt], (const unsigned*)&Bh);
                mma_bf16(c[mt][nt], (const unsigned*)&Ah[mt], (const unsigned*)&Bl);
                mma_bf16(c[mt][nt], (const unsigned*)&Al[mt], (const unsigned*)&Bh);
            }
        }
    }

    #pragma unroll
    for (int mt = 0; mt < 2; mt++) {
        int r0 = blockIdx.x * ROWS + warp_m * 32 + mt * 16 + g;
        #pragma unroll
        for (int nt = 0; nt < 8; nt++) {
            int col = (warp_n * 8 + nt) * 8 + 2 * t;
            if (r0 < nrows)
                *(__half2*)&H[(size_t)r0 * COUT + col] =
                    __floats2half2_rn(c[mt][nt][0], c[mt][nt][1]);
            if (r0 + 8 < nrows)
                *(__half2*)&H[(size_t)(r0 + 8) * COUT + col] =
                    __floats2half2_rn(c[mt][nt][2], c[mt][nt][3]);
        }
    }
}

// ---------------- fused softmax + aggregate (R6 form, single-edge loop) -----
#define LCACHE 128
template<int C, bool RELU, bool FUSE2>
__global__ void node_aggregate_kernel(const __half* __restrict__ h,
                                      const float* __restrict__ bias,
                                      float* __restrict__ out,
                                      const float* __restrict__ asrc,
                                      const float* __restrict__ adst) {
    __shared__ float lc[8][LCACHE];
    int warp = (blockIdx.x * blockDim.x + threadIdx.x) >> 5;
    int w    = (threadIdx.x >> 5);
    int lane = threadIdx.x & 31;
    if (warp >= N_NODES) return;
    int n   = warp;
    int beg = g_rowptr[n];
    int end = g_rowptr[n + 1];
    float ad = adst[n];

    float m = -CUDART_INF_F;
    for (int i = beg + lane; i < end; i += 32) {
        int s = g_csr_src[i];
        float l = asrc[s] + ad;
        l = (l > 0.0f) ? l : NEG_SLOPE * l;
        int off = i - beg;
        if (off < LCACHE) lc[w][off] = l;
        m = fmaxf(m, l);
    }
    #pragma unroll
    for (int o = 16; o > 0; o >>= 1)
        m = fmaxf(m, __shfl_xor_sync(0xffffffffu, m, o));
    __syncwarp();

    float den = 0.0f;
    float a0 = 0.f, a1 = 0.f, a2 = 0.f, a3 = 0.f;
    for (int i = beg; i < end; i++) {
        int off = i - beg;
        float l;
        if (off < LCACHE) {
            l = lc[w][off];
        } else {
            int s2 = g_csr_src[i];
            l = asrc[s2] + ad;
            l = (l > 0.0f) ? l : NEG_SLOPE * l;
        }
        float ev = __expf(l - m);
        den += ev;
        int s = g_csr_src[i];
        const __half* hp = h + (size_t)s * C;
        if (C == 128) {
            uint2 raw = ((const uint2*)hp)[lane];
            float2 f01 = __half22float2(*(const __half2*)&raw.x);
            float2 f23 = __half22float2(*(const __half2*)&raw.y);
            a0 += ev * f01.x; a1 += ev * f01.y;
            a2 += ev * f23.x; a3 += ev * f23.y;
        } else {
            __half2 raw = ((const __half2*)hp)[lane];
            float2 f = __half22float2(raw);
            a0 += ev * f.x; a1 += ev * f.y;
        }
    }

    float inv = 1.0f / (den + 1e-16f);
    if (C == 128) {
        float4 b = ((const float4*)bias)[lane];
        float4 r;
        r.x = a0 * inv + b.x; r.y = a1 * inv + b.y;
        r.z = a2 * inv + b.z; r.w = a3 * inv + b.w;
        if (RELU) {
            r.x = fmaxf(r.x, 0.f); r.y = fmaxf(r.y, 0.f);
            r.z = fmaxf(r.z, 0.f); r.w = fmaxf(r.w, 0.f);
        }
        if (FUSE2) {
            float4 ps = ((const float4*)g_p2)[lane];
            float4 pd = ((const float4*)(g_p2 + 128))[lane];
            float s2 = r.x * ps.x + r.y * ps.y + r.z * ps.z + r.w * ps.w;
            float d2 = r.x * pd.x + r.y * pd.y + r.z * pd.z + r.w * pd.w;
            #pragma unroll
            for (int o = 16; o > 0; o >>= 1) {
                s2 += __shfl_xor_sync(0xffffffffu, s2, o);
                d2 += __shfl_xor_sync(0xffffffffu, d2, o);
            }
            if (lane == 0) {
                g_asrc2[n] = s2;
                g_adst2[n] = d2;
            }
            write_frag_row(n, lane, r);
        } else {
            ((float4*)(out + (size_t)n * C))[lane] = r;
        }
    } else {
        float2 b = ((const float2*)bias)[lane];
        float2 r;
        r.x = a0 * inv + b.x; r.y = a1 * inv + b.y;
        if (RELU) { r.x = fmaxf(r.x, 0.f); r.y = fmaxf(r.y, 0.f); }
        ((float2*)(out + (size_t)n * C))[lane] = r;
    }
}

// ---------------- launch ----------------
extern "C" void kernel_launch(void* const* d_in, const int* in_sizes, int n_in,
                              void* d_out, int out_size) {
    const float* x   = (const float*)d_in[0];
    const int*   ei  = (const int*)d_in[1];
    const float* W1s = (const float*)d_in[2];
    const float* W1d = (const float*)d_in[3];
    const float* a1s = (const float*)d_in[4];
    const float* a1d = (const float*)d_in[5];
    const float* b1  = (const float*)d_in[6];
    const float* W2s = (const float*)d_in[7];
    const float* W2d = (const float*)d_in[8];
    const float* a2s = (const float*)d_in[9];
    const float* a2d = (const float*)d_in[10];
    const float* b2  = (const float*)d_in[11];
    float* out = (float*)d_out;

    const int* srcp = ei;
    const int* dstp = ei + N_EDGES;

    void *p_cnt, *p_h1, *p_h2, *p_WfH1, *p_WfL1, *p_WfH2, *p_WfL2;
    void *p_asrc, *p_adst, *p_asrc2, *p_adst2;
    cudaGetSymbolAddress(&p_cnt, g_cnt);
    cudaGetSymbolAddress(&p_h1, g_h1);
    cudaGetSymbolAddress(&p_h2, g_h2);
    cudaGetSymbolAddress(&p_WfH1, g_WfH1);
    cudaGetSymbolAddress(&p_WfL1, g_WfL1);
    cudaGetSymbolAddress(&p_WfH2, g_WfH2);
    cudaGetSymbolAddress(&p_WfL2, g_WfL2);
    cudaGetSymbolAddress(&p_asrc, g_asrc);
    cudaGetSymbolAddress(&p_adst, g_adst);
    cudaGetSymbolAddress(&p_asrc2, g_asrc2);
    cudaGetSymbolAddress(&p_adst2, g_adst2);
    __half* h1 = (__half*)p_h1;
    __half* h2 = (__half*)p_h2;

    static cudaStream_t s_side = nullptr;
    static cudaEvent_t ev_fork = nullptr, ev_join = nullptr;
    if (!s_side) {
        cudaStreamCreateWithFlags(&s_side, cudaStreamNonBlocking);
        cudaEventCreateWithFlags(&ev_fork, cudaEventDisableTiming);
        cudaEventCreateWithFlags(&ev_join, cudaEventDisableTiming);
    }

    const int TB = 256;
    const int edgeBlocks = (N_EDGES + TB - 1) / TB;
    const int nodeBlocks = (N_NODES + TB - 1) / TB;
    const int nodeWarpBlocks = (N_NODES * 32 + TB - 1) / TB;
    const int prepBlocks = (PAD_TILES * 16 * 32) / TB;

    // ---- fork event + side-stream memset (issued first; memsets aren't kernels) ----
    cudaEventRecord(ev_fork, 0);
    cudaStreamWaitEvent(s_side, ev_fork, 0);
    cudaMemsetAsync(p_cnt, 0, N_NODES * sizeof(int), s_side);

    // ---- main chain issued first so gemm_frag<128> is the 4th kernel (ncu window) ----
    compute_p_all_kernel<<<2, 128>>>(W1s, a1s, W1d, a1d, W2s, a2s, W2d, a2d);     // #1
    convertW_all_kernel<<<DIM_HID / 8 + DIM_OUT / 8, 256>>>(W1s, W2s);            // #2
    row_prep_kernel<<<prepBlocks, TB>>>(x);                                       // #3
    gemm_frag_kernel<DIM_HID><<<(N_NODES + 127) / 128, 256>>>(                    // #4 <- ncu
        h1, N_NODES, (unsigned*)p_WfH1, (unsigned*)p_WfL1);

    // ---- CSR build on side stream (concurrent with main chain via fork event) ----
    hist_kernel<<<edgeBlocks, TB, 0, s_side>>>(dstp);
    scan1_kernel<<<N_SCAN_BLOCKS, SCAN_BLK, 0, s_side>>>();
    scan2_kernel<<<1, 128, 0, s_side>>>();
    scan3_kernel<<<nodeBlocks, TB, 0, s_side>>>();
    scatter_kernel<<<edgeBlocks, TB, 0, s_side>>>(srcp, dstp);
    cudaEventRecord(ev_join, s_side);

    // ---- join: aggregate needs CSR + gemm1 ----
    cudaStreamWaitEvent(0, ev_join, 0);
    node_aggregate_kernel<DIM_HID, true, true><<<nodeWarpBlocks, TB>>>(
        h1, b1, nullptr, (const float*)p_asrc, (const float*)p_adst);
    gemm_frag_kernel<DIM_OUT><<<(N_NODES + 255) / 256, 256>>>(h2, N_NODES,
                                                              (unsigned*)p_WfH2, (unsigned*)p_WfL2);
    node_aggregate_kernel<DIM_OUT, false, false><<<nodeWarpBlocks, TB>>>(
        h2, b2, out, (const float*)p_asrc2, (const float*)p_adst2);

    (void)in_sizes; (void)n_in; (void)out_size;
}